// round 16
// baseline (speedup 1.0000x reference)
#include <cuda_runtime.h>
#include <cuda_bf16.h>

#define NVSEG 29000
#define HWSZ  (1024 * 1024)
#define BATCH 16
#define BHW   (BATCH * HWSZ)

// PDL device-side controls
#define GRIDDEP_WAIT()    asm volatile("griddepcontrol.wait;" ::: "memory")
#define GRIDDEP_LAUNCH()  asm volatile("griddepcontrol.launch_dependents;")

// __device__ globals are zero-initialized at module load.
// g_acc[v] = {sum_c0, sum_c1, sum_c2, count}. Invariant: zero at
// kernel_launch entry — replaced_kernel re-zeroes after consuming.
__device__ float4 g_acc[NVSEG];
__device__ float4 g_rep[NVSEG];

// Pass 1 (at its scattered-RED LTS floor): 2 px/thread, one float4 RED/px.
__global__ __launch_bounds__(256) void accumulate_kernel(
    const float* __restrict__ img, const int* __restrict__ seg)
{
    const long t = (long)blockIdx.x * blockDim.x + threadIdx.x;  // 0 .. BHW/2
    const long p = t << 1;
    const int  b = (int)(t >> 19);          // p >> 20
    const long rem = p & (HWSZ - 1);
    const float* base = img + (long)b * 3 * HWSZ + rem;

    const int2   s  = *(const int2*)(seg + p);
    const float2 c0 = *(const float2*)(base + 0 * HWSZ);
    const float2 c1 = *(const float2*)(base + 1 * HWSZ);
    const float2 c2 = *(const float2*)(base + 2 * HWSZ);

    GRIDDEP_LAUNCH();   // fire before the REDs; consumer wait provides safety

    atomicAdd(&g_acc[s.x], make_float4(c0.x, c1.x, c2.x, 1.0f));
    atomicAdd(&g_acc[s.y], make_float4(c0.y, c1.y, c2.y, 1.0f));
}

// Pass 2: rep[v] = fV[v] - sums[v]/max(cnt,1); reset g_acc[v] = 0.
// fV loads precede the wait (overlap accumulate's tail); launch_dependents
// fires right after the wait so output's blocks launch during this body.
__global__ __launch_bounds__(512) void replaced_kernel(const float* __restrict__ fV) {
    int v = blockIdx.x * blockDim.x + threadIdx.x;
    float f0 = 0.f, f1 = 0.f, f2 = 0.f;
    if (v < NVSEG) {
        f0 = fV[3 * v + 0];
        f1 = fV[3 * v + 1];
        f2 = fV[3 * v + 2];
    }
    GRIDDEP_WAIT();     // all accumulate REDs visible after this
    GRIDDEP_LAUNCH();   // output may launch now; its wait gates on our completion
    if (v < NVSEG) {
        float4 a = g_acc[v];
        g_acc[v] = make_float4(0.f, 0.f, 0.f, 0.f);
        float inv = 1.0f / fmaxf(a.w, 1.0f);
        float4 r;
        r.x = f0 - a.x * inv;
        r.y = f1 - a.y * inv;
        r.z = f2 - a.z * inv;
        r.w = 0.f;
        g_rep[v] = r;
    }
}

// Pass 3 (at its L1tex gather-replay floor): 4 px/thread, 512-thr blocks
// (single changed variable: fewer/larger CTAs, full 64-warp residency at
// 4 CTAs/SM). seg + img loads precede the wait; gathers after.
__global__ __launch_bounds__(512) void output_kernel(
    const float* __restrict__ img, const int* __restrict__ seg,
    float* __restrict__ out)
{
    const long t = (long)blockIdx.x * blockDim.x + threadIdx.x;
    const long p = t << 2;
    const int  b = (int)(t >> 18);
    const long rem = p & (HWSZ - 1);
    const float* base = img + (long)b * 3 * HWSZ + rem;

    const int4   s  = *(const int4*)(seg + p);
    const float4 c0 = *(const float4*)(base + 0 * HWSZ);
    const float4 c1 = *(const float4*)(base + 1 * HWSZ);
    const float4 c2 = *(const float4*)(base + 2 * HWSZ);

    GRIDDEP_WAIT();     // g_rep writes visible after this

    const float4 r0 = g_rep[s.x];
    const float4 r1 = g_rep[s.y];
    const float4 r2 = g_rep[s.z];
    const float4 r3 = g_rep[s.w];

    float4 o0, o1, o2;
    o0.x = c0.x + r0.x;  o0.y = c1.x + r0.y;  o0.z = c2.x + r0.z;  o0.w = c0.y + r1.x;
    o1.x = c1.y + r1.y;  o1.y = c2.y + r1.z;  o1.z = c0.z + r2.x;  o1.w = c1.z + r2.y;
    o2.x = c2.z + r2.z;  o2.y = c0.w + r3.x;  o2.z = c1.w + r3.y;  o2.w = c2.w + r3.z;

    float4* dst = (float4*)(out + p * 3);   // 12t floats -> 16B aligned
    dst[0] = o0;
    dst[1] = o1;
    dst[2] = o2;
}

extern "C" void kernel_launch(void* const* d_in, const int* in_sizes, int n_in,
                              void* d_out, int out_size)
{
    const float* img = (const float*)d_in[0];
    const int*   seg = (const int*)d_in[1];
    const float* fV  = (const float*)d_in[2];
    float* out = (float*)d_out;

    const int nvBlocks  = (NVSEG + 511) / 512;
    const int accBlocks = (BHW / 2) / 256;   // 32768
    const int outBlocks = (BHW / 4) / 512;   // 8192

    accumulate_kernel<<<accBlocks, 256>>>(img, seg);

    cudaLaunchAttribute attr[1];
    attr[0].id = cudaLaunchAttributeProgrammaticStreamSerialization;
    attr[0].val.programmaticStreamSerializationAllowed = 1;

    cudaLaunchConfig_t cfg1 = {};
    cfg1.gridDim = dim3(nvBlocks);
    cfg1.blockDim = dim3(512);
    cfg1.attrs = attr;
    cfg1.numAttrs = 1;
    cudaLaunchKernelEx(&cfg1, replaced_kernel, fV);

    cudaLaunchConfig_t cfg2 = {};
    cfg2.gridDim = dim3(outBlocks);
    cfg2.blockDim = dim3(512);
    cfg2.attrs = attr;
    cfg2.numAttrs = 1;
    cudaLaunchKernelEx(&cfg2, output_kernel, img, seg, out);
}

// round 17
// speedup vs baseline: 1.0019x; 1.0019x over previous
#include <cuda_runtime.h>
#include <cuda_bf16.h>

#define NVSEG 29000
#define HWSZ  (1024 * 1024)
#define BATCH 16
#define BHW   (BATCH * HWSZ)

// PDL device-side controls
#define GRIDDEP_WAIT()    asm volatile("griddepcontrol.wait;" ::: "memory")
#define GRIDDEP_LAUNCH()  asm volatile("griddepcontrol.launch_dependents;")

// __device__ globals are zero-initialized at module load.
// g_acc[v] = {sum_c0, sum_c1, sum_c2, count}. Invariant: zero at
// kernel_launch entry — replaced_kernel re-zeroes after consuming.
__device__ float4 g_acc[NVSEG];
__device__ float4 g_rep[NVSEG];

// Pass 1 (at its scattered-RED LTS floor): 2 px/thread, one float4 RED/px.
// 512-thr blocks (single probe vs R14): same warps/SM, half the CTAs.
__global__ __launch_bounds__(512) void accumulate_kernel(
    const float* __restrict__ img, const int* __restrict__ seg)
{
    const long t = (long)blockIdx.x * blockDim.x + threadIdx.x;  // 0 .. BHW/2
    const long p = t << 1;
    const int  b = (int)(t >> 19);          // p >> 20
    const long rem = p & (HWSZ - 1);
    const float* base = img + (long)b * 3 * HWSZ + rem;

    const int2   s  = *(const int2*)(seg + p);
    const float2 c0 = *(const float2*)(base + 0 * HWSZ);
    const float2 c1 = *(const float2*)(base + 1 * HWSZ);
    const float2 c2 = *(const float2*)(base + 2 * HWSZ);

    GRIDDEP_LAUNCH();   // fire before the REDs; consumer wait provides safety

    atomicAdd(&g_acc[s.x], make_float4(c0.x, c1.x, c2.x, 1.0f));
    atomicAdd(&g_acc[s.y], make_float4(c0.y, c1.y, c2.y, 1.0f));
}

// Pass 2: rep[v] = fV[v] - sums[v]/max(cnt,1); reset g_acc[v] = 0.
// fV loads precede the wait (overlap accumulate's tail); launch_dependents
// fires right after the wait so output's blocks launch during this body.
__global__ __launch_bounds__(512) void replaced_kernel(const float* __restrict__ fV) {
    int v = blockIdx.x * blockDim.x + threadIdx.x;
    float f0 = 0.f, f1 = 0.f, f2 = 0.f;
    if (v < NVSEG) {
        f0 = fV[3 * v + 0];
        f1 = fV[3 * v + 1];
        f2 = fV[3 * v + 2];
    }
    GRIDDEP_WAIT();     // all accumulate REDs visible after this
    GRIDDEP_LAUNCH();   // output may launch now; its wait gates on our completion
    if (v < NVSEG) {
        float4 a = g_acc[v];
        g_acc[v] = make_float4(0.f, 0.f, 0.f, 0.f);
        float inv = 1.0f / fmaxf(a.w, 1.0f);
        float4 r;
        r.x = f0 - a.x * inv;
        r.y = f1 - a.y * inv;
        r.z = f2 - a.z * inv;
        r.w = 0.f;
        g_rep[v] = r;
    }
}

// Pass 3 (at its L1tex gather-replay floor, best-measured form): 4 px/thread,
// 256-thr blocks. seg + img loads precede the wait; gathers after.
__global__ __launch_bounds__(256) void output_kernel(
    const float* __restrict__ img, const int* __restrict__ seg,
    float* __restrict__ out)
{
    const long t = (long)blockIdx.x * blockDim.x + threadIdx.x;
    const long p = t << 2;
    const int  b = (int)(t >> 18);
    const long rem = p & (HWSZ - 1);
    const float* base = img + (long)b * 3 * HWSZ + rem;

    const int4   s  = *(const int4*)(seg + p);
    const float4 c0 = *(const float4*)(base + 0 * HWSZ);
    const float4 c1 = *(const float4*)(base + 1 * HWSZ);
    const float4 c2 = *(const float4*)(base + 2 * HWSZ);

    GRIDDEP_WAIT();     // g_rep writes visible after this

    const float4 r0 = g_rep[s.x];
    const float4 r1 = g_rep[s.y];
    const float4 r2 = g_rep[s.z];
    const float4 r3 = g_rep[s.w];

    float4 o0, o1, o2;
    o0.x = c0.x + r0.x;  o0.y = c1.x + r0.y;  o0.z = c2.x + r0.z;  o0.w = c0.y + r1.x;
    o1.x = c1.y + r1.y;  o1.y = c2.y + r1.z;  o1.z = c0.z + r2.x;  o1.w = c1.z + r2.y;
    o2.x = c2.z + r2.z;  o2.y = c0.w + r3.x;  o2.z = c1.w + r3.y;  o2.w = c2.w + r3.z;

    float4* dst = (float4*)(out + p * 3);   // 12t floats -> 16B aligned
    dst[0] = o0;
    dst[1] = o1;
    dst[2] = o2;
}

extern "C" void kernel_launch(void* const* d_in, const int* in_sizes, int n_in,
                              void* d_out, int out_size)
{
    const float* img = (const float*)d_in[0];
    const int*   seg = (const int*)d_in[1];
    const float* fV  = (const float*)d_in[2];
    float* out = (float*)d_out;

    const int nvBlocks  = (NVSEG + 511) / 512;
    const int accBlocks = (BHW / 2) / 512;   // 16384
    const int outBlocks = (BHW / 4) / 256;   // 16384

    accumulate_kernel<<<accBlocks, 512>>>(img, seg);

    cudaLaunchAttribute attr[1];
    attr[0].id = cudaLaunchAttributeProgrammaticStreamSerialization;
    attr[0].val.programmaticStreamSerializationAllowed = 1;

    cudaLaunchConfig_t cfg1 = {};
    cfg1.gridDim = dim3(nvBlocks);
    cfg1.blockDim = dim3(512);
    cfg1.attrs = attr;
    cfg1.numAttrs = 1;
    cudaLaunchKernelEx(&cfg1, replaced_kernel, fV);

    cudaLaunchConfig_t cfg2 = {};
    cfg2.gridDim = dim3(outBlocks);
    cfg2.blockDim = dim3(256);
    cfg2.attrs = attr;
    cfg2.numAttrs = 1;
    cudaLaunchKernelEx(&cfg2, output_kernel, img, seg, out);
}